// round 10
// baseline (speedup 1.0000x reference)
#include <cuda_runtime.h>

// ============================================================================
// Convert2ImageLayer: out[b,h,w,:] = feat[b, slic[b,h,w]-1, :]  (0 if invalid)
// Shapes: B=8, N=1024, C=128, H=W=512.
//
// R10 probe: combine the two independently-measured good properties:
//   - MLP=4 independent gathers per thread (R2's win; R9 had only 2)
//   - 256-bit LDG/STG (halved L1tex wavefront count; R9's idea)
// Warp owns P=8 pixels; lane owns 32B chunk c8 of pixel-pair half; each
// thread issues 4 independent LDG.256 + 4 coalesced STG.256 (1KB bursts).
// ============================================================================

static constexpr int  Nc = 1024;
static constexpr int  Cf = 128;           // floats per pixel row
static constexpr int  HW_SHIFT = 18;      // H*W = 2^18 pixels per batch image
static constexpr long long PIX = 8LL << HW_SHIFT;   // 2,097,152 pixels
static constexpr int  P = 8;              // pixels per warp (4 pairs)

__device__ __forceinline__ void ldg256(const float* __restrict__ p, float r[8]) {
    asm volatile("ld.global.v8.f32 {%0,%1,%2,%3,%4,%5,%6,%7}, [%8];"
                 : "=f"(r[0]), "=f"(r[1]), "=f"(r[2]), "=f"(r[3]),
                   "=f"(r[4]), "=f"(r[5]), "=f"(r[6]), "=f"(r[7])
                 : "l"(p));
}

__device__ __forceinline__ void stg256_cs(float* __restrict__ p, const float r[8]) {
    asm volatile("st.global.cs.v8.f32 [%0], {%1,%2,%3,%4,%5,%6,%7,%8};"
                 :: "l"(p),
                    "f"(r[0]), "f"(r[1]), "f"(r[2]), "f"(r[3]),
                    "f"(r[4]), "f"(r[5]), "f"(r[6]), "f"(r[7])
                 : "memory");
}

__global__ void __launch_bounds__(256)
convert2image_gather_v8x4(const float* __restrict__ feat,   // [B, N, C]
                          const int*   __restrict__ slic,   // [B*H*W]
                          float*       __restrict__ out)    // [B*H*W, C]
{
    const long long warp_gid = (long long)blockIdx.x * (blockDim.x >> 5)
                             + (threadIdx.x >> 5);
    const long long pix0 = warp_gid * P;
    const int lane = threadIdx.x & 31;
    const int half = lane >> 4;            // which pixel within a pair
    const int c8   = lane & 15;            // which 32B chunk of the 512B row

    if (pix0 >= PIX) return;

    // All P pixels of a warp lie in the same batch image (P divides H*W).
    const int b = (int)(pix0 >> HW_SHIFT);
    const float* __restrict__ fb = feat + ((long long)b * Nc) * Cf;

    // Lanes 0..P-1 fetch the P segment labels (one 32B sector total).
    int myidx = 0;
    if (lane < P) myidx = __ldg(slic + pix0 + lane) - 1;   // labels 1-indexed

    // Four INDEPENDENT 256-bit gathers: pair j covers pixels {2j, 2j+1}.
    float v[4][8];
    #pragma unroll
    for (int j = 0; j < 4; j++) {
        const int idx = __shfl_sync(0xffffffffu, myidx, 2 * j + half);
        #pragma unroll
        for (int k = 0; k < 8; k++) v[j][k] = 0.f;
        if ((unsigned)idx < (unsigned)Nc) {
            ldg256(fb + (long long)idx * Cf + c8 * 8, v[j]);   // MLP=4
        }
    }

    // Four coalesced 1KB streaming store bursts (write-once, evict-first).
    float* __restrict__ o = out + (pix0 << 7) + (long long)half * Cf + c8 * 8;
    #pragma unroll
    for (int j = 0; j < 4; j++) {
        stg256_cs(o + (long long)(2 * j) * Cf, v[j]);
    }
}

extern "C" void kernel_launch(void* const* d_in, const int* in_sizes, int n_in,
                              void* d_out, int out_size)
{
    const float* feat = (const float*)d_in[0];   // graph_lstm_output fp32 [B,N,C]
    const int*   slic = (const int*)d_in[1];     // slic_output int32 [B,H,W,1]
    float*       out  = (float*)d_out;           // fp32 [B,H,W,C]

    const int threads = 256;                      // 8 warps -> 64 pixels/block
    const long long pixels_per_block = (threads / 32) * P;
    const unsigned blocks = (unsigned)((PIX + pixels_per_block - 1) / pixels_per_block); // 32,768

    convert2image_gather_v8x4<<<blocks, threads>>>(feat, slic, out);
}

// round 11
// speedup vs baseline: 1.1012x; 1.1012x over previous
#include <cuda_runtime.h>

// ============================================================================
// Convert2ImageLayer: out[b,h,w,:] = feat[b, slic[b,h,w]-1, :]  (0 if invalid)
// Shapes: B=8, N=1024, C=128, H=W=512.
//
// FINAL kernel — HBM-write-roofline reached.
//   compulsory traffic: 1.074 GB output writes (+12 MB reads) -> 134 us floor
//   measured: 141.8 us best / ~143 us typical = 7.6 TB/s = 95% of 8 TB/s spec
//
// Measured conclusions (10 rounds):
//   - MLP=4 independent LDG.128 gathers per thread is the entire win
//     (260 us -> 142 us); MLP>4 gives nothing (ptxas reuse / occupancy).
//   - Fine scheduling granularity wins: 65536 small CTAs of 8 warps; all
//     coarser variants (P=8, 512-thr blocks, software pipelines) 1-4 us worse.
//   - 256-bit LDG/STG (sm_100 v8.f32) measured WORSE both times tried:
//     halves per-thread MLP or costs registers/occupancy; wavefronts don't
//     actually halve.
//   - __stcs streaming stores keep the 4MB feature table cache-resident.
// ============================================================================

static constexpr int  Nc = 1024;
static constexpr int  C4 = 32;            // 128 floats = 32 float4 per pixel
static constexpr int  HW_SHIFT = 18;      // H*W = 2^18 pixels per batch image
static constexpr long long PIX = 8LL << HW_SHIFT;   // 2,097,152 pixels
static constexpr int  P = 4;              // pixels per warp (measured optimum)

__global__ void __launch_bounds__(256)
convert2image_gather4(const float4* __restrict__ feat,   // [B, N, C/4]
                      const int*    __restrict__ slic,   // [B*H*W]
                      float4*       __restrict__ out)    // [B*H*W, C/4]
{
    const long long warp_gid = (long long)blockIdx.x * (blockDim.x >> 5)
                             + (threadIdx.x >> 5);
    const long long pix0 = warp_gid * P;
    const int lane = threadIdx.x & 31;

    if (pix0 >= PIX) return;

    // All P pixels of a warp lie in the same batch image (P divides H*W).
    const int b = (int)(pix0 >> HW_SHIFT);
    const float4* __restrict__ fb = feat + ((long long)b * Nc) * C4;

    // Lanes 0..P-1 fetch the P segment labels (one 16B sector total).
    int myidx = 0;
    if (lane < P) myidx = __ldg(slic + pix0 + lane) - 1;   // labels 1-indexed

    float4 v[P];
    #pragma unroll
    for (int p = 0; p < P; p++) {
        const int idx = __shfl_sync(0xffffffffu, myidx, p);
        v[p] = make_float4(0.f, 0.f, 0.f, 0.f);
        if ((unsigned)idx < (unsigned)Nc) {
            v[p] = __ldg(fb + (long long)idx * C4 + lane);  // independent -> MLP=P
        }
    }

    float4* __restrict__ o = out + (pix0 << 5) + lane;
    #pragma unroll
    for (int p = 0; p < P; p++) {
        __stcs(o + (p << 5), v[p]);    // streaming: write-once, evict-first
    }
}

extern "C" void kernel_launch(void* const* d_in, const int* in_sizes, int n_in,
                              void* d_out, int out_size)
{
    const float4* feat = (const float4*)d_in[0];   // graph_lstm_output fp32 [B,N,C]
    const int*    slic = (const int*)d_in[1];      // slic_output int32 [B,H,W,1]
    float4*       out  = (float4*)d_out;           // fp32 [B,H,W,C]

    const int threads = 256;                        // 8 warps -> 32 pixels/block
    const long long pixels_per_block = (threads / 32) * P;
    const unsigned blocks = (unsigned)((PIX + pixels_per_block - 1) / pixels_per_block); // 65,536

    convert2image_gather4<<<blocks, threads>>>(feat, slic, out);
}